// round 10
// baseline (speedup 1.0000x reference)
#include <cuda_runtime.h>
#include <cuda_bf16.h>
#include <math.h>
#include <stdint.h>

// Problem shapes (fixed): B=4, S=2048, D=1024, H=1024
#define PB 4
#define PS 2048
#define PD 1024
#define PH 1024
#define PM (PB * PS)          // 8192 rows
#define EPSQ 1e-8f

// ---------------------------------------------------------------------------
// Static device scratch (allocation forbidden)
// ---------------------------------------------------------------------------
__device__ float g_v[(size_t)PM * (3 * PH)];                 // 8192 x 3072
__device__ float g_q[(size_t)PM * (4 * PH)];                 // 8192 x 4096 (states)
__device__ float g_wr[(size_t)PD * (4 * PH)];                // rna-rounded W_out
__device__ __nv_bfloat16 g_ab[(size_t)PM * (3 * PD)];        // x split [hi|lo|hi]
__device__ __nv_bfloat16 g_bb[(size_t)(3 * PH) * (3 * PD)];  // W_in split [hi|hi|lo]

// ---------------------------------------------------------------------------
// Helpers
// ---------------------------------------------------------------------------
__device__ __forceinline__ uint32_t smem_u32(const void* p) {
    uint32_t a;
    asm("{ .reg .u64 t; cvta.to.shared.u64 t, %1; cvt.u32.u64 %0, t; }" : "=r"(a) : "l"(p));
    return a;
}
__device__ __forceinline__ float tf32r(float a) {
    float r;
    asm("cvt.rna.tf32.f32 %0, %1;" : "=f"(r) : "f"(a));
    return r;
}
__device__ __forceinline__ void cp_async16(uint32_t dst, const void* src) {
    asm volatile("cp.async.cg.shared.global [%0], [%1], 16;" :: "r"(dst), "l"(src));
}

#define MMA_TF32(acc, a0, a1, a2, a3, b0, b1) \
    asm volatile("mma.sync.aligned.m16n8k8.row.col.f32.tf32.tf32.f32 " \
        "{%0,%1,%2,%3}, {%4,%5,%6,%7}, {%8,%9}, {%0,%1,%2,%3};" \
        : "+f"((acc)[0]), "+f"((acc)[1]), "+f"((acc)[2]), "+f"((acc)[3]) \
        : "r"(a0), "r"(a1), "r"(a2), "r"(a3), "r"(b0), "r"(b1))

#define MMA_BF16(acc, a0, a1, a2, a3, b0, b1) \
    asm volatile("mma.sync.aligned.m16n8k16.row.col.f32.bf16.bf16.f32 " \
        "{%0,%1,%2,%3}, {%4,%5,%6,%7}, {%8,%9}, {%0,%1,%2,%3};" \
        : "+f"((acc)[0]), "+f"((acc)[1]), "+f"((acc)[2]), "+f"((acc)[3]) \
        : "r"(a0), "r"(a1), "r"(a2), "r"(a3), "r"(b0), "r"(b1))

// ---------------------------------------------------------------------------
// Unified mma.sync GEMM: C[M,N] = A[M,K] * B[N,K]^T + bias[N]
// CTA 128(M) x 256(N), 8 warps as 2(M) x 4(N), warp tile 64x64
// ((mt,nt) = (4,8): 32 FLOP/smem-byte bf16, 16 tf32 — vs 21/10.7 at (4,4)).
// k-tile = 128 bytes/row, 4-stage cp.async pipeline, XOR-swizzled smem,
// 1 CTA/SM (acc = 128 regs).
//   BF16 == 1: bf16 elements, MMA m16n8k16;  BF16 == 0: fp32/tf32, m16n8k8
// K is in ELEMENTS.
// ---------------------------------------------------------------------------
#define BM 128
#define BN 256
#define GSTAGES 4
#define A_BYTES 16384              // 128 rows x 128B
#define STAGE_BYTES 49152          // A 16KB + B 32KB
#define GSMEM (GSTAGES * STAGE_BYTES)

template<int BF16>
__global__ __launch_bounds__(256)
void gemm_mma(const char* __restrict__ A, const char* __restrict__ B,
              const float* __restrict__ bias, float* __restrict__ C,
              int N, int K) {
    extern __shared__ char smem[];
    const uint32_t sbase = smem_u32(smem);

    const int ESIZE = BF16 ? 2 : 4;
    const int KE = 128 / ESIZE;
    const int T = K / KE;

    const int tid = threadIdx.x;
    const int lane = tid & 31;
    const int wid = tid >> 5;
    const int wm = wid & 1;        // M warp (2)
    const int wn = wid >> 1;       // N warp (4) -> 64 cols each
    const int crow = blockIdx.y * BM;
    const int ccol = blockIdx.x * BN;

    const size_t rowBytes = (size_t)K * ESIZE;
    const char* Abase = A + (size_t)crow * rowBytes;
    const char* Bbase = B + (size_t)ccol * rowBytes;

    const int aHalf = lane >> 4;
    uint32_t aOff[4], aSwz[4];
#pragma unroll
    for (int mt = 0; mt < 4; mt++) {
        int r = wm * 64 + mt * 16 + (lane & 15);
        aOff[mt] = r * 128;
        aSwz[mt] = r & 7;
    }
    const int bHalf = (lane >> 3) & 1;
    uint32_t bOff[4], bSwz[4];
#pragma unroll
    for (int ntp = 0; ntp < 4; ntp++) {
        int r = wn * 64 + ntp * 16 + (lane & 7) + ((lane >> 4) << 3);
        bOff[ntp] = r * 128;
        bSwz[ntp] = r & 7;
    }

    float acc[4][8][4];
#pragma unroll
    for (int mt = 0; mt < 4; mt++)
#pragma unroll
        for (int nt = 0; nt < 8; nt++)
#pragma unroll
            for (int j = 0; j < 4; j++) acc[mt][nt][j] = 0.0f;

// 4 A chunks (128 rows x 8 c16 = 1024) + 8 B chunks (256 rows x 8 = 2048)
#define ISSUE(kt, stg) do { \
    _Pragma("unroll") \
    for (int _i = 0; _i < 4; _i++) { \
        int _s = tid + _i * 256; \
        int _row = _s >> 3, _c16 = _s & 7; \
        uint32_t _off = _row * 128 + ((_c16 ^ (_row & 7)) << 4); \
        cp_async16(sbase + (stg) * STAGE_BYTES + _off, \
                   Abase + (size_t)_row * rowBytes + (kt) * 128 + _c16 * 16); \
    } \
    _Pragma("unroll") \
    for (int _i = 0; _i < 8; _i++) { \
        int _s = tid + _i * 256; \
        int _row = _s >> 3, _c16 = _s & 7; \
        uint32_t _off = _row * 128 + ((_c16 ^ (_row & 7)) << 4); \
        cp_async16(sbase + (stg) * STAGE_BYTES + A_BYTES + _off, \
                   Bbase + (size_t)_row * rowBytes + (kt) * 128 + _c16 * 16); \
    } \
} while (0)

    // prologue: 3 tiles in flight
    ISSUE(0, 0);
    asm volatile("cp.async.commit_group;" ::: "memory");
    if (T > 1) ISSUE(1, 1);
    asm volatile("cp.async.commit_group;" ::: "memory");
    if (T > 2) ISSUE(2, 2);
    asm volatile("cp.async.commit_group;" ::: "memory");

    for (int it = 0; it < T; ++it) {
        asm volatile("cp.async.wait_group 2;" ::: "memory");
        __syncthreads();
        if (it + 3 < T) ISSUE(it + 3, (it + 3) % GSTAGES);
        asm volatile("cp.async.commit_group;" ::: "memory");

        const uint32_t sA = sbase + (it % GSTAGES) * STAGE_BYTES;
        const uint32_t sB = sA + A_BYTES;
#pragma unroll
        for (int ks = 0; ks < 4; ks++) {
            uint32_t aF[4][4];
#pragma unroll
            for (int mt = 0; mt < 4; mt++) {
                uint32_t ad = sA + aOff[mt] + (((2 * ks + aHalf) ^ aSwz[mt]) << 4);
                asm volatile("ldmatrix.sync.aligned.m8n8.x4.shared.b16 {%0,%1,%2,%3}, [%4];"
                    : "=r"(aF[mt][0]), "=r"(aF[mt][1]), "=r"(aF[mt][2]), "=r"(aF[mt][3])
                    : "r"(ad));
            }
            uint32_t bF[8][2];
#pragma unroll
            for (int ntp = 0; ntp < 4; ntp++) {
                uint32_t bd = sB + bOff[ntp] + (((2 * ks + bHalf) ^ bSwz[ntp]) << 4);
                asm volatile("ldmatrix.sync.aligned.m8n8.x4.shared.b16 {%0,%1,%2,%3}, [%4];"
                    : "=r"(bF[2 * ntp][0]), "=r"(bF[2 * ntp][1]),
                      "=r"(bF[2 * ntp + 1][0]), "=r"(bF[2 * ntp + 1][1])
                    : "r"(bd));
            }
#pragma unroll
            for (int mt = 0; mt < 4; mt++)
#pragma unroll
                for (int nt = 0; nt < 8; nt++) {
                    if constexpr (BF16) {
                        MMA_BF16(acc[mt][nt], aF[mt][0], aF[mt][1], aF[mt][2], aF[mt][3],
                                 bF[nt][0], bF[nt][1]);
                    } else {
                        MMA_TF32(acc[mt][nt], aF[mt][0], aF[mt][1], aF[mt][2], aF[mt][3],
                                 bF[nt][0], bF[nt][1]);
                    }
                }
        }
    }

    const int g = lane >> 2, tg = lane & 3;
#pragma unroll
    for (int mt = 0; mt < 4; mt++) {
        int r0 = crow + wm * 64 + mt * 16 + g;
#pragma unroll
        for (int nt = 0; nt < 8; nt++) {
            int col = ccol + wn * 64 + nt * 8 + 2 * tg;
            float2 bv = *(const float2*)(bias + col);
            float2 o0 = make_float2(acc[mt][nt][0] + bv.x, acc[mt][nt][1] + bv.y);
            float2 o1 = make_float2(acc[mt][nt][2] + bv.x, acc[mt][nt][3] + bv.y);
            *(float2*)(C + (size_t)r0 * N + col) = o0;
            *(float2*)(C + (size_t)(r0 + 8) * N + col) = o1;
        }
    }
#undef ISSUE
}

// ---------------------------------------------------------------------------
// bf16 3-term split: in (R x K fp32) -> out (R x 3K bf16)
//   modeB=0 (A): [hi | lo | hi];  modeB=1 (B): [hi | hi | lo]
// ---------------------------------------------------------------------------
__global__ void split_bf16_kernel(const float* __restrict__ in,
                                  __nv_bfloat16* __restrict__ out,
                                  int K, int modeB, size_t total4) {
    size_t s = (size_t)blockIdx.x * blockDim.x + threadIdx.x;
    if (s >= total4) return;
    int K4 = K >> 2;
    size_t row = s / K4;
    int c4 = (int)(s - row * K4);
    float4 a = ((const float4*)in)[s];
    float av[4] = {a.x, a.y, a.z, a.w};
    __nv_bfloat16 h[4], l[4];
#pragma unroll
    for (int i = 0; i < 4; i++) {
        h[i] = __float2bfloat16_rn(av[i]);
        l[i] = __float2bfloat16_rn(av[i] - __bfloat162float(h[i]));
    }
    __nv_bfloat162 hv0, hv1, lv0, lv1;
    hv0.x = h[0]; hv0.y = h[1]; hv1.x = h[2]; hv1.y = h[3];
    lv0.x = l[0]; lv0.y = l[1]; lv1.x = l[2]; lv1.y = l[3];
    __nv_bfloat16* orow = out + row * (size_t)(3 * K);
    __nv_bfloat162* p0 = (__nv_bfloat162*)(orow + c4 * 4);
    __nv_bfloat162* p1 = (__nv_bfloat162*)(orow + K + c4 * 4);
    __nv_bfloat162* p2 = (__nv_bfloat162*)(orow + 2 * K + c4 * 4);
    p0[0] = hv0; p0[1] = hv1;
    if (modeB) { p1[0] = hv0; p1[1] = hv1; p2[0] = lv0; p2[1] = lv1; }
    else       { p1[0] = lv0; p1[1] = lv1; p2[0] = hv0; p2[1] = hv1; }
}

// ---------------------------------------------------------------------------
// rna tf32 rounding (elementwise)
// ---------------------------------------------------------------------------
__global__ void round_tf32_kernel(const float* __restrict__ in, float* __restrict__ out,
                                  size_t total4) {
    size_t s = (size_t)blockIdx.x * blockDim.x + threadIdx.x;
    if (s >= total4) return;
    float4 a = ((const float4*)in)[s];
    float4 r;
    r.x = tf32r(a.x); r.y = tf32r(a.y); r.z = tf32r(a.z); r.w = tf32r(a.w);
    ((float4*)out)[s] = r;
}

// ---------------------------------------------------------------------------
// Quaternion helpers (float4 = w,x,y,z)
// ---------------------------------------------------------------------------
__device__ __forceinline__ float4 qmul(float4 a, float4 b) {
    return make_float4(
        a.x * b.x - a.y * b.y - a.z * b.z - a.w * b.w,
        a.x * b.y + a.y * b.x + a.z * b.w - a.w * b.z,
        a.x * b.z - a.y * b.w + a.z * b.x + a.w * b.y,
        a.x * b.w + a.y * b.z - a.z * b.y + a.w * b.x);
}
__device__ __forceinline__ float4 qnorm(float4 a) {
    float n = sqrtf(a.x * a.x + a.y * a.y + a.z * a.z + a.w * a.w);
    float s = 1.0f / (n + EPSQ);
    return make_float4(a.x * s, a.y * s, a.z * s, a.w * s);
}

// ---------------------------------------------------------------------------
// Fused SU(2) exp map + parallel prefix quaternion product per (b,h) chain.
// (Round-7 config: grid B*H = 4096 blocks x 256 thr.)
// ---------------------------------------------------------------------------
__global__ __launch_bounds__(256)
void quat_scan_kernel(const float* __restrict__ v, float* __restrict__ states,
                      float* __restrict__ mfinal) {
    const int b = blockIdx.x >> 10;
    const int h = blockIdx.x & 1023;
    const int t = threadIdx.x;

    float4 loc[8];
#pragma unroll
    for (int j = 0; j < 8; j++) {
        const int s = t * 8 + j;
        const float* vp = v + ((size_t)b * PS + s) * (3 * PH) + h * 3;
        float vx = vp[0], vy = vp[1], vz = vp[2];
        float th = sqrtf(vx * vx + vy * vy + vz * vz);
        float sn, cs;
        sincosf(th, &sn, &cs);
        float inv = sn / (th + EPSQ);
        loc[j] = make_float4(cs, vx * inv, vy * inv, vz * inv);
    }

    float4 agg = loc[0];
#pragma unroll
    for (int j = 1; j < 8; j++) agg = qmul(loc[j], agg);

    __shared__ float4 sbuf[256];
    sbuf[t] = agg;
    __syncthreads();
#pragma unroll
    for (int d = 1; d < 256; d <<= 1) {
        float4 other;
        const bool has = (t >= d);
        if (has) other = sbuf[t - d];
        __syncthreads();
        if (has) sbuf[t] = qmul(sbuf[t], other);
        __syncthreads();
    }
    float4 p = make_float4(1.0f, 0.0f, 0.0f, 0.0f);
    if (t > 0) p = sbuf[t - 1];

    const size_t base = ((size_t)b * PS * PH + h) * 4;
#pragma unroll
    for (int j = 0; j < 8; j++) {
        p = qmul(loc[j], p);
        float4 outq = qnorm(p);
        float4 outr = make_float4(tf32r(outq.x), tf32r(outq.y),
                                  tf32r(outq.z), tf32r(outq.w));
        *(float4*)(states + base + (size_t)(t * 8 + j) * (PH * 4)) = outr;
        if (t == 255 && j == 7)
            *(float4*)(mfinal + (size_t)blockIdx.x * 4) = outq;
    }
}

// ---------------------------------------------------------------------------
extern "C" void kernel_launch(void* const* d_in, const int* in_sizes, int n_in,
                              void* d_out, int out_size) {
    const float* x     = (const float*)d_in[0];   // (B,S,D)
    const float* W_in  = (const float*)d_in[1];   // (3H, D)
    const float* b_in  = (const float*)d_in[2];   // (3H)
    const float* W_out = (const float*)d_in[3];   // (D, 4H)
    const float* b_out = (const float*)d_in[4];   // (D)
    float* out = (float*)d_out;
    float* full_output = out;                      // (B,S,D)
    float* m_final     = out + (size_t)PM * PD;    // (B,H,4)

    float *v_ptr, *q_ptr, *wr;
    __nv_bfloat16 *ab, *bb;
    cudaGetSymbolAddress((void**)&v_ptr, g_v);
    cudaGetSymbolAddress((void**)&q_ptr, g_q);
    cudaGetSymbolAddress((void**)&wr, g_wr);
    cudaGetSymbolAddress((void**)&ab, g_ab);
    cudaGetSymbolAddress((void**)&bb, g_bb);

    cudaFuncSetAttribute(gemm_mma<1>, cudaFuncAttributeMaxDynamicSharedMemorySize, GSMEM);
    cudaFuncSetAttribute(gemm_mma<0>, cudaFuncAttributeMaxDynamicSharedMemorySize, GSMEM);

    // bf16 3-term split of x and W_in (K 1024 -> 3072 bf16)
    {
        size_t t4 = (size_t)PM * PD / 4;
        split_bf16_kernel<<<(unsigned)((t4 + 255) / 256), 256>>>(x, ab, PD, 0, t4);
        t4 = (size_t)(3 * PH) * PD / 4;
        split_bf16_kernel<<<(unsigned)((t4 + 255) / 256), 256>>>(W_in, bb, PD, 1, t4);
    }
    // GEMM1: v = x W_in^T + b_in  (M=8192, N=3072, K'=3072 bf16 3-term)
    {
        dim3 grid(3 * PH / BN, PM / BM);
        gemm_mma<1><<<grid, 256, GSMEM>>>((const char*)ab, (const char*)bb,
                                          b_in, v_ptr, 3 * PH, 3 * PD);
    }
    // rna-round W_out (removes HW-truncation bias in GEMM2)
    {
        size_t t4 = (size_t)PD * (4 * PH) / 4;
        round_tf32_kernel<<<(unsigned)((t4 + 255) / 256), 256>>>(W_out, wr, t4);
    }
    // fused exp-map + prefix quaternion scan (+ m_final)
    quat_scan_kernel<<<PB * PH, 256>>>(v_ptr, q_ptr, m_final);
    // GEMM2: out = states W_out^T + b_out  (M=8192, N=1024, K=4096 tf32)
    {
        dim3 grid(PD / BN, PM / BM);
        gemm_mma<0><<<grid, 256, GSMEM>>>((const char*)q_ptr, (const char*)wr,
                                          b_out, full_output, PD, 4 * PH);
    }
}

// round 11
// speedup vs baseline: 1.1648x; 1.1648x over previous
#include <cuda_runtime.h>
#include <cuda_bf16.h>
#include <math.h>
#include <stdint.h>

// Problem shapes (fixed): B=4, S=2048, D=1024, H=1024
#define PB 4
#define PS 2048
#define PD 1024
#define PH 1024
#define PM (PB * PS)          // 8192 rows
#define EPSQ 1e-8f

// scan decomposition: 16 chunks x 8 subs x 16 elements = 2048 = S
#define NC 16
#define NW 8
#define NE 16

// ---------------------------------------------------------------------------
// Static device scratch (allocation forbidden)
// ---------------------------------------------------------------------------
__device__ float g_v[(size_t)PM * (3 * PH)];                 // 8192 x 3072
__device__ float g_q[(size_t)PM * (4 * PH)];                 // 8192 x 4096 (states)
__device__ float g_wr[(size_t)PD * (4 * PH)];                // rna-rounded W_out
__device__ __nv_bfloat16 g_ab[(size_t)PM * (3 * PD)];        // x split [hi|lo|hi]
__device__ __nv_bfloat16 g_bb[(size_t)(3 * PH) * (3 * PD)];  // W_in split [hi|hi|lo]
__device__ float g_sub[(size_t)PB * NC * NW * PH * 4];       // sub aggregates
__device__ float g_part[(size_t)PB * NC * PH * 4];           // chunk totals -> prefixes

// ---------------------------------------------------------------------------
// Helpers
// ---------------------------------------------------------------------------
__device__ __forceinline__ uint32_t smem_u32(const void* p) {
    uint32_t a;
    asm("{ .reg .u64 t; cvta.to.shared.u64 t, %1; cvt.u32.u64 %0, t; }" : "=r"(a) : "l"(p));
    return a;
}
__device__ __forceinline__ float tf32r(float a) {
    float r;
    asm("cvt.rna.tf32.f32 %0, %1;" : "=f"(r) : "f"(a));
    return r;
}
__device__ __forceinline__ void cp_async16(uint32_t dst, const void* src) {
    asm volatile("cp.async.cg.shared.global [%0], [%1], 16;" :: "r"(dst), "l"(src));
}

#define MMA_TF32(acc, a0, a1, a2, a3, b0, b1) \
    asm volatile("mma.sync.aligned.m16n8k8.row.col.f32.tf32.tf32.f32 " \
        "{%0,%1,%2,%3}, {%4,%5,%6,%7}, {%8,%9}, {%0,%1,%2,%3};" \
        : "+f"((acc)[0]), "+f"((acc)[1]), "+f"((acc)[2]), "+f"((acc)[3]) \
        : "r"(a0), "r"(a1), "r"(a2), "r"(a3), "r"(b0), "r"(b1))

#define MMA_BF16(acc, a0, a1, a2, a3, b0, b1) \
    asm volatile("mma.sync.aligned.m16n8k16.row.col.f32.bf16.bf16.f32 " \
        "{%0,%1,%2,%3}, {%4,%5,%6,%7}, {%8,%9}, {%0,%1,%2,%3};" \
        : "+f"((acc)[0]), "+f"((acc)[1]), "+f"((acc)[2]), "+f"((acc)[3]) \
        : "r"(a0), "r"(a1), "r"(a2), "r"(a3), "r"(b0), "r"(b1))

// ---------------------------------------------------------------------------
// Unified mma.sync GEMM (round-7 config: CTA 128x128, 8 warps 2Mx4N of 64x32,
// 3-stage cp.async, XOR swizzle, 2 CTAs/SM naturally).
//   BF16 == 1: bf16 elements, MMA m16n8k16;  BF16 == 0: fp32/tf32, m16n8k8
// K is in ELEMENTS.
// ---------------------------------------------------------------------------
#define BM 128
#define BN 128
#define GSTAGES 3
#define STAGE_BYTES 32768          // A 16KB + B 16KB
#define GSMEM (GSTAGES * STAGE_BYTES)

template<int BF16>
__global__ __launch_bounds__(256)
void gemm_mma(const char* __restrict__ A, const char* __restrict__ B,
              const float* __restrict__ bias, float* __restrict__ C,
              int N, int K) {
    extern __shared__ char smem[];
    const uint32_t sbase = smem_u32(smem);

    const int ESIZE = BF16 ? 2 : 4;
    const int KE = 128 / ESIZE;
    const int T = K / KE;

    const int tid = threadIdx.x;
    const int lane = tid & 31;
    const int wid = tid >> 5;
    const int wm = wid & 1;
    const int wn = wid >> 1;
    const int crow = blockIdx.y * BM;
    const int ccol = blockIdx.x * BN;

    const size_t rowBytes = (size_t)K * ESIZE;
    const char* Abase = A + (size_t)crow * rowBytes;
    const char* Bbase = B + (size_t)ccol * rowBytes;

    const int aHalf = lane >> 4;
    uint32_t aOff[4], aSwz[4];
#pragma unroll
    for (int mt = 0; mt < 4; mt++) {
        int r = wm * 64 + mt * 16 + (lane & 15);
        aOff[mt] = r * 128;
        aSwz[mt] = r & 7;
    }
    const int bHalf = (lane >> 3) & 1;
    uint32_t bOff[2], bSwz[2];
#pragma unroll
    for (int ntp = 0; ntp < 2; ntp++) {
        int r = wn * 32 + ntp * 16 + (lane & 7) + ((lane >> 4) << 3);
        bOff[ntp] = r * 128;
        bSwz[ntp] = r & 7;
    }

    float acc[4][4][4];
#pragma unroll
    for (int mt = 0; mt < 4; mt++)
#pragma unroll
        for (int nt = 0; nt < 4; nt++)
#pragma unroll
            for (int j = 0; j < 4; j++) acc[mt][nt][j] = 0.0f;

#define ISSUE(kt, stg) do { \
    _Pragma("unroll") \
    for (int _i = 0; _i < 4; _i++) { \
        int _s = tid + _i * 256; \
        int _row = _s >> 3, _c16 = _s & 7; \
        uint32_t _off = _row * 128 + ((_c16 ^ (_row & 7)) << 4); \
        const char* _asrc = Abase + (size_t)_row * rowBytes + (kt) * 128 + _c16 * 16; \
        const char* _bsrc = Bbase + (size_t)_row * rowBytes + (kt) * 128 + _c16 * 16; \
        cp_async16(sbase + (stg) * STAGE_BYTES + _off, _asrc); \
        cp_async16(sbase + (stg) * STAGE_BYTES + 16384 + _off, _bsrc); \
    } \
} while (0)

    ISSUE(0, 0);
    asm volatile("cp.async.commit_group;" ::: "memory");
    ISSUE(1, 1);
    asm volatile("cp.async.commit_group;" ::: "memory");

    for (int it = 0; it < T; ++it) {
        asm volatile("cp.async.wait_group 1;" ::: "memory");
        __syncthreads();
        if (it + 2 < T) ISSUE(it + 2, (it + 2) % GSTAGES);
        asm volatile("cp.async.commit_group;" ::: "memory");

        const uint32_t sA = sbase + (it % GSTAGES) * STAGE_BYTES;
        const uint32_t sB = sA + 16384;
#pragma unroll
        for (int ks = 0; ks < 4; ks++) {
            uint32_t aF[4][4];
#pragma unroll
            for (int mt = 0; mt < 4; mt++) {
                uint32_t ad = sA + aOff[mt] + (((2 * ks + aHalf) ^ aSwz[mt]) << 4);
                asm volatile("ldmatrix.sync.aligned.m8n8.x4.shared.b16 {%0,%1,%2,%3}, [%4];"
                    : "=r"(aF[mt][0]), "=r"(aF[mt][1]), "=r"(aF[mt][2]), "=r"(aF[mt][3])
                    : "r"(ad));
            }
            uint32_t bF[4][2];
#pragma unroll
            for (int ntp = 0; ntp < 2; ntp++) {
                uint32_t bd = sB + bOff[ntp] + (((2 * ks + bHalf) ^ bSwz[ntp]) << 4);
                asm volatile("ldmatrix.sync.aligned.m8n8.x4.shared.b16 {%0,%1,%2,%3}, [%4];"
                    : "=r"(bF[2 * ntp][0]), "=r"(bF[2 * ntp][1]),
                      "=r"(bF[2 * ntp + 1][0]), "=r"(bF[2 * ntp + 1][1])
                    : "r"(bd));
            }
#pragma unroll
            for (int mt = 0; mt < 4; mt++)
#pragma unroll
                for (int nt = 0; nt < 4; nt++) {
                    if constexpr (BF16) {
                        MMA_BF16(acc[mt][nt], aF[mt][0], aF[mt][1], aF[mt][2], aF[mt][3],
                                 bF[nt][0], bF[nt][1]);
                    } else {
                        MMA_TF32(acc[mt][nt], aF[mt][0], aF[mt][1], aF[mt][2], aF[mt][3],
                                 bF[nt][0], bF[nt][1]);
                    }
                }
        }
    }

    const int g = lane >> 2, tg = lane & 3;
#pragma unroll
    for (int mt = 0; mt < 4; mt++) {
        int r0 = crow + wm * 64 + mt * 16 + g;
#pragma unroll
        for (int nt = 0; nt < 4; nt++) {
            int col = ccol + wn * 32 + nt * 8 + 2 * tg;
            float2 bv = *(const float2*)(bias + col);
            float2 o0 = make_float2(acc[mt][nt][0] + bv.x, acc[mt][nt][1] + bv.y);
            float2 o1 = make_float2(acc[mt][nt][2] + bv.x, acc[mt][nt][3] + bv.y);
            *(float2*)(C + (size_t)r0 * N + col) = o0;
            *(float2*)(C + (size_t)(r0 + 8) * N + col) = o1;
        }
    }
#undef ISSUE
}

// ---------------------------------------------------------------------------
// bf16 3-term split: in (R x K fp32) -> out (R x 3K bf16)
//   modeB=0 (A): [hi | lo | hi];  modeB=1 (B): [hi | hi | lo]
// ---------------------------------------------------------------------------
__global__ void split_bf16_kernel(const float* __restrict__ in,
                                  __nv_bfloat16* __restrict__ out,
                                  int K, int modeB, size_t total4) {
    size_t s = (size_t)blockIdx.x * blockDim.x + threadIdx.x;
    if (s >= total4) return;
    int K4 = K >> 2;
    size_t row = s / K4;
    int c4 = (int)(s - row * K4);
    float4 a = ((const float4*)in)[s];
    float av[4] = {a.x, a.y, a.z, a.w};
    __nv_bfloat16 h[4], l[4];
#pragma unroll
    for (int i = 0; i < 4; i++) {
        h[i] = __float2bfloat16_rn(av[i]);
        l[i] = __float2bfloat16_rn(av[i] - __bfloat162float(h[i]));
    }
    __nv_bfloat162 hv0, hv1, lv0, lv1;
    hv0.x = h[0]; hv0.y = h[1]; hv1.x = h[2]; hv1.y = h[3];
    lv0.x = l[0]; lv0.y = l[1]; lv1.x = l[2]; lv1.y = l[3];
    __nv_bfloat16* orow = out + row * (size_t)(3 * K);
    __nv_bfloat162* p0 = (__nv_bfloat162*)(orow + c4 * 4);
    __nv_bfloat162* p1 = (__nv_bfloat162*)(orow + K + c4 * 4);
    __nv_bfloat162* p2 = (__nv_bfloat162*)(orow + 2 * K + c4 * 4);
    p0[0] = hv0; p0[1] = hv1;
    if (modeB) { p1[0] = hv0; p1[1] = hv1; p2[0] = lv0; p2[1] = lv1; }
    else       { p1[0] = lv0; p1[1] = lv1; p2[0] = hv0; p2[1] = hv1; }
}

// ---------------------------------------------------------------------------
// rna tf32 rounding (elementwise)
// ---------------------------------------------------------------------------
__global__ void round_tf32_kernel(const float* __restrict__ in, float* __restrict__ out,
                                  size_t total4) {
    size_t s = (size_t)blockIdx.x * blockDim.x + threadIdx.x;
    if (s >= total4) return;
    float4 a = ((const float4*)in)[s];
    float4 r;
    r.x = tf32r(a.x); r.y = tf32r(a.y); r.z = tf32r(a.z); r.w = tf32r(a.w);
    ((float4*)out)[s] = r;
}

// ---------------------------------------------------------------------------
// Quaternion helpers (float4 = w,x,y,z)
// ---------------------------------------------------------------------------
__device__ __forceinline__ float4 qmul(float4 a, float4 b) {
    return make_float4(
        a.x * b.x - a.y * b.y - a.z * b.z - a.w * b.w,
        a.x * b.y + a.y * b.x + a.z * b.w - a.w * b.z,
        a.x * b.z - a.y * b.w + a.z * b.x + a.w * b.y,
        a.x * b.w + a.y * b.z - a.z * b.y + a.w * b.x);
}
__device__ __forceinline__ float4 qnorm(float4 a) {
    float n = sqrtf(a.x * a.x + a.y * a.y + a.z * a.z + a.w * a.w);
    float s = 1.0f / (n + EPSQ);
    return make_float4(a.x * s, a.y * s, a.z * s, a.w * s);
}
__device__ __forceinline__ float4 qfromv3(float vx, float vy, float vz) {
    float th = sqrtf(vx * vx + vy * vy + vz * vz);
    float sn, cs;
    sincosf(th, &sn, &cs);
    float inv = sn / (th + EPSQ);
    return make_float4(cs, vx * inv, vy * inv, vz * inv);
}

// ---------------------------------------------------------------------------
// Three-phase coalesced quaternion scan.
// Grid A/C: B * NC * (H/32) = 2048 blocks, 256 threads = 32 h-lanes x NW subs.
// All v reads are 384B-contiguous rows; states writes 512B-contiguous.
// Newer-index-on-the-LEFT at every combine level.
// ---------------------------------------------------------------------------
__global__ __launch_bounds__(256)
void scanA_kernel(const float* __restrict__ v, float* __restrict__ sub,
                  float* __restrict__ part) {
    const int lane = threadIdx.x & 31;
    const int w    = threadIdx.x >> 5;           // sub 0..7
    const int hg   = blockIdx.x & 31;
    const int c    = (blockIdx.x >> 5) & (NC - 1);
    const int b    = blockIdx.x >> 9;
    const int h    = hg * 32 + lane;

    // aggregate 16 elements (newest on left)
    float4 agg = make_float4(1.0f, 0.0f, 0.0f, 0.0f);
    {
        const int s0 = c * (NW * NE) + w * NE;
        const float* vp = v + ((size_t)(b * PS + s0)) * (3 * PH) + h * 3;
        for (int i = 0; i < NE; i++) {
            agg = qmul(qfromv3(vp[0], vp[1], vp[2]), agg);
            vp += 3 * PH;
        }
    }
    // store sub aggregate (coalesced over h)
    *(float4*)(sub + ((((size_t)b * NC + c) * NW + w) * PH + h) * 4) = agg;

    // chunk total = agg7 * agg6 * ... * agg0
    __shared__ float4 sb[NW][32];
    sb[w][lane] = agg;
    __syncthreads();
    if (w == 0) {
        float4 tot = sb[0][lane];
#pragma unroll
        for (int j = 1; j < NW; j++) tot = qmul(sb[j][lane], tot);
        *(float4*)(part + (((size_t)b * NC + c) * PH + h) * 4) = tot;
    }
}

// Exclusive scan of chunk totals along c for each (b,h). 4096 threads.
__global__ __launch_bounds__(512)
void scanB_kernel(float* __restrict__ part) {
    const int gt = blockIdx.x * 512 + threadIdx.x;   // 0..4095
    const int b = gt >> 10;
    const int h = gt & 1023;
    float4 pref = make_float4(1.0f, 0.0f, 0.0f, 0.0f);
    for (int c = 0; c < NC; c++) {
        float4* p = (float4*)(part + (((size_t)b * NC + c) * PH + h) * 4);
        float4 tot = *p;
        *p = pref;                 // overwrite with EXCLUSIVE prefix
        pref = qmul(tot, pref);    // newer chunk on left
    }
}

__global__ __launch_bounds__(256)
void scanC_kernel(const float* __restrict__ v, const float* __restrict__ sub,
                  const float* __restrict__ part, float* __restrict__ states,
                  float* __restrict__ mfinal) {
    const int lane = threadIdx.x & 31;
    const int w    = threadIdx.x >> 5;
    const int hg   = blockIdx.x & 31;
    const int c    = (blockIdx.x >> 5) & (NC - 1);
    const int b    = blockIdx.x >> 9;
    const int h    = hg * 32 + lane;

    // prefix = (subs w-1..0 of this chunk) * (chunk exclusive prefix)
    float4 p = *(const float4*)(part + (((size_t)b * NC + c) * PH + h) * 4);
    for (int j = 0; j < w; j++) {
        float4 sj = *(const float4*)(sub + ((((size_t)b * NC + c) * NW + j) * PH + h) * 4);
        p = qmul(sj, p);
    }

    const int s0 = c * (NW * NE) + w * NE;
    const float* vp = v + ((size_t)(b * PS + s0)) * (3 * PH) + h * 3;
    float* sp = states + (((size_t)(b * PS + s0)) * PH + h) * 4;
    for (int i = 0; i < NE; i++) {
        p = qmul(qfromv3(vp[0], vp[1], vp[2]), p);
        float4 oq = qnorm(p);
        *(float4*)sp = make_float4(tf32r(oq.x), tf32r(oq.y), tf32r(oq.z), tf32r(oq.w));
        if (c == NC - 1 && w == NW - 1 && i == NE - 1)
            *(float4*)(mfinal + ((size_t)b * PH + h) * 4) = oq;
        vp += 3 * PH;
        sp += (size_t)PH * 4;
    }
}

// ---------------------------------------------------------------------------
extern "C" void kernel_launch(void* const* d_in, const int* in_sizes, int n_in,
                              void* d_out, int out_size) {
    const float* x     = (const float*)d_in[0];   // (B,S,D)
    const float* W_in  = (const float*)d_in[1];   // (3H, D)
    const float* b_in  = (const float*)d_in[2];   // (3H)
    const float* W_out = (const float*)d_in[3];   // (D, 4H)
    const float* b_out = (const float*)d_in[4];   // (D)
    float* out = (float*)d_out;
    float* full_output = out;                      // (B,S,D)
    float* m_final     = out + (size_t)PM * PD;    // (B,H,4)

    float *v_ptr, *q_ptr, *wr, *subp, *partp;
    __nv_bfloat16 *ab, *bb;
    cudaGetSymbolAddress((void**)&v_ptr, g_v);
    cudaGetSymbolAddress((void**)&q_ptr, g_q);
    cudaGetSymbolAddress((void**)&wr, g_wr);
    cudaGetSymbolAddress((void**)&ab, g_ab);
    cudaGetSymbolAddress((void**)&bb, g_bb);
    cudaGetSymbolAddress((void**)&subp, g_sub);
    cudaGetSymbolAddress((void**)&partp, g_part);

    cudaFuncSetAttribute(gemm_mma<1>, cudaFuncAttributeMaxDynamicSharedMemorySize, GSMEM);
    cudaFuncSetAttribute(gemm_mma<0>, cudaFuncAttributeMaxDynamicSharedMemorySize, GSMEM);

    // bf16 3-term split of x and W_in (K 1024 -> 3072 bf16)
    {
        size_t t4 = (size_t)PM * PD / 4;
        split_bf16_kernel<<<(unsigned)((t4 + 255) / 256), 256>>>(x, ab, PD, 0, t4);
        t4 = (size_t)(3 * PH) * PD / 4;
        split_bf16_kernel<<<(unsigned)((t4 + 255) / 256), 256>>>(W_in, bb, PD, 1, t4);
    }
    // GEMM1: v = x W_in^T + b_in  (M=8192, N=3072, K'=3072 bf16 3-term)
    {
        dim3 grid(3 * PH / BN, PM / BM);
        gemm_mma<1><<<grid, 256, GSMEM>>>((const char*)ab, (const char*)bb,
                                          b_in, v_ptr, 3 * PH, 3 * PD);
    }
    // rna-round W_out (removes HW-truncation bias in GEMM2)
    {
        size_t t4 = (size_t)PD * (4 * PH) / 4;
        round_tf32_kernel<<<(unsigned)((t4 + 255) / 256), 256>>>(W_out, wr, t4);
    }
    // three-phase coalesced exp-map + prefix quaternion scan (+ m_final)
    {
        const unsigned gridAC = PB * NC * (PH / 32);   // 2048
        scanA_kernel<<<gridAC, 256>>>(v_ptr, subp, partp);
        scanB_kernel<<<PB * PH / 512, 512>>>(partp);
        scanC_kernel<<<gridAC, 256>>>(v_ptr, subp, partp, q_ptr, m_final);
    }
    // GEMM2: out = states W_out^T + b_out  (M=8192, N=1024, K=4096 tf32)
    {
        dim3 grid(PD / BN, PM / BM);
        gemm_mma<0><<<grid, 256, GSMEM>>>((const char*)q_ptr, (const char*)wr,
                                          b_out, full_output, PD, 4 * PH);
    }
}

// round 12
// speedup vs baseline: 1.1716x; 1.0059x over previous
#include <cuda_runtime.h>
#include <cuda_bf16.h>
#include <math.h>
#include <stdint.h>

// Problem shapes (fixed): B=4, S=2048, D=1024, H=1024
#define PB 4
#define PS 2048
#define PD 1024
#define PH 1024
#define PM (PB * PS)          // 8192 rows
#define EPSQ 1e-8f

// scan decomposition: 16 chunks x 8 subs x 16 elements = 2048 = S
#define NC 16
#define NW 8
#define NE 16

// ---------------------------------------------------------------------------
// Static device scratch (allocation forbidden)
// ---------------------------------------------------------------------------
__device__ float g_v[(size_t)PM * (3 * PH)];                 // 8192 x 3072
__device__ float g_q[(size_t)PM * (4 * PH)];                 // 8192 x 4096 (states)
__device__ float g_wr[(size_t)PD * (4 * PH)];                // rna-rounded W_out
__device__ __nv_bfloat16 g_ab[(size_t)PM * (3 * PD)];        // x split [hi|lo|hi]
__device__ __nv_bfloat16 g_bb[(size_t)(3 * PH) * (3 * PD)];  // W_in split [hi|hi|lo]
__device__ float g_sub[(size_t)PB * NC * NW * PH * 4];       // sub aggregates
__device__ float g_part[(size_t)PB * NC * PH * 4];           // chunk TOTALS

// ---------------------------------------------------------------------------
// Helpers
// ---------------------------------------------------------------------------
__device__ __forceinline__ uint32_t smem_u32(const void* p) {
    uint32_t a;
    asm("{ .reg .u64 t; cvta.to.shared.u64 t, %1; cvt.u32.u64 %0, t; }" : "=r"(a) : "l"(p));
    return a;
}
__device__ __forceinline__ float tf32r(float a) {
    float r;
    asm("cvt.rna.tf32.f32 %0, %1;" : "=f"(r) : "f"(a));
    return r;
}
__device__ __forceinline__ void cp_async16(uint32_t dst, const void* src) {
    asm volatile("cp.async.cg.shared.global [%0], [%1], 16;" :: "r"(dst), "l"(src));
}

#define MMA_TF32(acc, a0, a1, a2, a3, b0, b1) \
    asm volatile("mma.sync.aligned.m16n8k8.row.col.f32.tf32.tf32.f32 " \
        "{%0,%1,%2,%3}, {%4,%5,%6,%7}, {%8,%9}, {%0,%1,%2,%3};" \
        : "+f"((acc)[0]), "+f"((acc)[1]), "+f"((acc)[2]), "+f"((acc)[3]) \
        : "r"(a0), "r"(a1), "r"(a2), "r"(a3), "r"(b0), "r"(b1))

#define MMA_BF16(acc, a0, a1, a2, a3, b0, b1) \
    asm volatile("mma.sync.aligned.m16n8k16.row.col.f32.bf16.bf16.f32 " \
        "{%0,%1,%2,%3}, {%4,%5,%6,%7}, {%8,%9}, {%0,%1,%2,%3};" \
        : "+f"((acc)[0]), "+f"((acc)[1]), "+f"((acc)[2]), "+f"((acc)[3]) \
        : "r"(a0), "r"(a1), "r"(a2), "r"(a3), "r"(b0), "r"(b1))

// ---------------------------------------------------------------------------
// Unified mma.sync GEMM (proven config: CTA 128x128, 8 warps 2Mx4N of 64x32,
// 3-stage cp.async, XOR swizzle, 2 CTAs/SM).
//   BF16 == 1: bf16 elements, MMA m16n8k16;  BF16 == 0: fp32/tf32, m16n8k8
// K is in ELEMENTS.
// ---------------------------------------------------------------------------
#define BM 128
#define BN 128
#define GSTAGES 3
#define STAGE_BYTES 32768          // A 16KB + B 16KB
#define GSMEM (GSTAGES * STAGE_BYTES)

template<int BF16>
__global__ __launch_bounds__(256)
void gemm_mma(const char* __restrict__ A, const char* __restrict__ B,
              const float* __restrict__ bias, float* __restrict__ C,
              int N, int K) {
    extern __shared__ char smem[];
    const uint32_t sbase = smem_u32(smem);

    const int ESIZE = BF16 ? 2 : 4;
    const int KE = 128 / ESIZE;
    const int T = K / KE;

    const int tid = threadIdx.x;
    const int lane = tid & 31;
    const int wid = tid >> 5;
    const int wm = wid & 1;
    const int wn = wid >> 1;
    const int crow = blockIdx.y * BM;
    const int ccol = blockIdx.x * BN;

    const size_t rowBytes = (size_t)K * ESIZE;
    const char* Abase = A + (size_t)crow * rowBytes;
    const char* Bbase = B + (size_t)ccol * rowBytes;

    const int aHalf = lane >> 4;
    uint32_t aOff[4], aSwz[4];
#pragma unroll
    for (int mt = 0; mt < 4; mt++) {
        int r = wm * 64 + mt * 16 + (lane & 15);
        aOff[mt] = r * 128;
        aSwz[mt] = r & 7;
    }
    const int bHalf = (lane >> 3) & 1;
    uint32_t bOff[2], bSwz[2];
#pragma unroll
    for (int ntp = 0; ntp < 2; ntp++) {
        int r = wn * 32 + ntp * 16 + (lane & 7) + ((lane >> 4) << 3);
        bOff[ntp] = r * 128;
        bSwz[ntp] = r & 7;
    }

    float acc[4][4][4];
#pragma unroll
    for (int mt = 0; mt < 4; mt++)
#pragma unroll
        for (int nt = 0; nt < 4; nt++)
#pragma unroll
            for (int j = 0; j < 4; j++) acc[mt][nt][j] = 0.0f;

#define ISSUE(kt, stg) do { \
    _Pragma("unroll") \
    for (int _i = 0; _i < 4; _i++) { \
        int _s = tid + _i * 256; \
        int _row = _s >> 3, _c16 = _s & 7; \
        uint32_t _off = _row * 128 + ((_c16 ^ (_row & 7)) << 4); \
        const char* _asrc = Abase + (size_t)_row * rowBytes + (kt) * 128 + _c16 * 16; \
        const char* _bsrc = Bbase + (size_t)_row * rowBytes + (kt) * 128 + _c16 * 16; \
        cp_async16(sbase + (stg) * STAGE_BYTES + _off, _asrc); \
        cp_async16(sbase + (stg) * STAGE_BYTES + 16384 + _off, _bsrc); \
    } \
} while (0)

    ISSUE(0, 0);
    asm volatile("cp.async.commit_group;" ::: "memory");
    ISSUE(1, 1);
    asm volatile("cp.async.commit_group;" ::: "memory");

    for (int it = 0; it < T; ++it) {
        asm volatile("cp.async.wait_group 1;" ::: "memory");
        __syncthreads();
        if (it + 2 < T) ISSUE(it + 2, (it + 2) % GSTAGES);
        asm volatile("cp.async.commit_group;" ::: "memory");

        const uint32_t sA = sbase + (it % GSTAGES) * STAGE_BYTES;
        const uint32_t sB = sA + 16384;
#pragma unroll
        for (int ks = 0; ks < 4; ks++) {
            uint32_t aF[4][4];
#pragma unroll
            for (int mt = 0; mt < 4; mt++) {
                uint32_t ad = sA + aOff[mt] + (((2 * ks + aHalf) ^ aSwz[mt]) << 4);
                asm volatile("ldmatrix.sync.aligned.m8n8.x4.shared.b16 {%0,%1,%2,%3}, [%4];"
                    : "=r"(aF[mt][0]), "=r"(aF[mt][1]), "=r"(aF[mt][2]), "=r"(aF[mt][3])
                    : "r"(ad));
            }
            uint32_t bF[4][2];
#pragma unroll
            for (int ntp = 0; ntp < 2; ntp++) {
                uint32_t bd = sB + bOff[ntp] + (((2 * ks + bHalf) ^ bSwz[ntp]) << 4);
                asm volatile("ldmatrix.sync.aligned.m8n8.x4.shared.b16 {%0,%1,%2,%3}, [%4];"
                    : "=r"(bF[2 * ntp][0]), "=r"(bF[2 * ntp][1]),
                      "=r"(bF[2 * ntp + 1][0]), "=r"(bF[2 * ntp + 1][1])
                    : "r"(bd));
            }
#pragma unroll
            for (int mt = 0; mt < 4; mt++)
#pragma unroll
                for (int nt = 0; nt < 4; nt++) {
                    if constexpr (BF16) {
                        MMA_BF16(acc[mt][nt], aF[mt][0], aF[mt][1], aF[mt][2], aF[mt][3],
                                 bF[nt][0], bF[nt][1]);
                    } else {
                        MMA_TF32(acc[mt][nt], aF[mt][0], aF[mt][1], aF[mt][2], aF[mt][3],
                                 bF[nt][0], bF[nt][1]);
                    }
                }
        }
    }

    const int g = lane >> 2, tg = lane & 3;
#pragma unroll
    for (int mt = 0; mt < 4; mt++) {
        int r0 = crow + wm * 64 + mt * 16 + g;
#pragma unroll
        for (int nt = 0; nt < 4; nt++) {
            int col = ccol + wn * 32 + nt * 8 + 2 * tg;
            float2 bv = *(const float2*)(bias + col);
            float2 o0 = make_float2(acc[mt][nt][0] + bv.x, acc[mt][nt][1] + bv.y);
            float2 o1 = make_float2(acc[mt][nt][2] + bv.x, acc[mt][nt][3] + bv.y);
            *(float2*)(C + (size_t)r0 * N + col) = o0;
            *(float2*)(C + (size_t)(r0 + 8) * N + col) = o1;
        }
    }
#undef ISSUE
}

// ---------------------------------------------------------------------------
// Fused prep kernel (one launch): region 0 = x bf16-split [hi|lo|hi],
// region 1 = W_in bf16-split [hi|hi|lo], region 2 = W_out rna-tf32 round.
// ---------------------------------------------------------------------------
#define PREP_T0 ((size_t)PM * PD / 4)              // 2,097,152
#define PREP_T1 ((size_t)(3 * PH) * PD / 4)        //   786,432
#define PREP_T2 ((size_t)PD * (4 * PH) / 4)        // 1,048,576
#define PREP_TOTAL (PREP_T0 + PREP_T1 + PREP_T2)

__device__ __forceinline__ void split_bf16_one(const float* __restrict__ in,
                                               __nv_bfloat16* __restrict__ out,
                                               int K, int modeB, size_t s) {
    int K4 = K >> 2;
    size_t row = s / K4;
    int c4 = (int)(s - row * K4);
    float4 a = ((const float4*)in)[s];
    float av[4] = {a.x, a.y, a.z, a.w};
    __nv_bfloat16 h[4], l[4];
#pragma unroll
    for (int i = 0; i < 4; i++) {
        h[i] = __float2bfloat16_rn(av[i]);
        l[i] = __float2bfloat16_rn(av[i] - __bfloat162float(h[i]));
    }
    __nv_bfloat162 hv0, hv1, lv0, lv1;
    hv0.x = h[0]; hv0.y = h[1]; hv1.x = h[2]; hv1.y = h[3];
    lv0.x = l[0]; lv0.y = l[1]; lv1.x = l[2]; lv1.y = l[3];
    __nv_bfloat16* orow = out + row * (size_t)(3 * K);
    __nv_bfloat162* p0 = (__nv_bfloat162*)(orow + c4 * 4);
    __nv_bfloat162* p1 = (__nv_bfloat162*)(orow + K + c4 * 4);
    __nv_bfloat162* p2 = (__nv_bfloat162*)(orow + 2 * K + c4 * 4);
    p0[0] = hv0; p0[1] = hv1;
    if (modeB) { p1[0] = hv0; p1[1] = hv1; p2[0] = lv0; p2[1] = lv1; }
    else       { p1[0] = lv0; p1[1] = lv1; p2[0] = hv0; p2[1] = hv1; }
}

__global__ __launch_bounds__(256)
void prep_kernel(const float* __restrict__ x, const float* __restrict__ W_in,
                 const float* __restrict__ W_out,
                 __nv_bfloat16* __restrict__ ab, __nv_bfloat16* __restrict__ bb,
                 float* __restrict__ wr) {
    size_t gid = (size_t)blockIdx.x * 256 + threadIdx.x;
    if (gid < PREP_T0) {
        split_bf16_one(x, ab, PD, 0, gid);
    } else if (gid < PREP_T0 + PREP_T1) {
        split_bf16_one(W_in, bb, PD, 1, gid - PREP_T0);
    } else if (gid < PREP_TOTAL) {
        size_t s = gid - PREP_T0 - PREP_T1;
        float4 a = ((const float4*)W_out)[s];
        float4 r;
        r.x = tf32r(a.x); r.y = tf32r(a.y); r.z = tf32r(a.z); r.w = tf32r(a.w);
        ((float4*)wr)[s] = r;
    }
}

// ---------------------------------------------------------------------------
// Quaternion helpers (float4 = w,x,y,z)
// ---------------------------------------------------------------------------
__device__ __forceinline__ float4 qmul(float4 a, float4 b) {
    return make_float4(
        a.x * b.x - a.y * b.y - a.z * b.z - a.w * b.w,
        a.x * b.y + a.y * b.x + a.z * b.w - a.w * b.z,
        a.x * b.z - a.y * b.w + a.z * b.x + a.w * b.y,
        a.x * b.w + a.y * b.z - a.z * b.y + a.w * b.x);
}
__device__ __forceinline__ float4 qnorm(float4 a) {
    float n = sqrtf(a.x * a.x + a.y * a.y + a.z * a.z + a.w * a.w);
    float s = 1.0f / (n + EPSQ);
    return make_float4(a.x * s, a.y * s, a.z * s, a.w * s);
}
__device__ __forceinline__ float4 qfromv3(float vx, float vy, float vz) {
    float th = sqrtf(vx * vx + vy * vy + vz * vz);
    float sn, cs;
    sincosf(th, &sn, &cs);
    float inv = sn / (th + EPSQ);
    return make_float4(cs, vx * inv, vy * inv, vz * inv);
}

// ---------------------------------------------------------------------------
// Two-phase coalesced quaternion scan (exclusive chunk-prefix folded into C).
// Grid A/C: B * NC * (H/32) = 2048 blocks, 256 threads = 32 h-lanes x NW subs.
// Newer-index-on-the-LEFT at every combine level.
// ---------------------------------------------------------------------------
__global__ __launch_bounds__(256)
void scanA_kernel(const float* __restrict__ v, float* __restrict__ sub,
                  float* __restrict__ part) {
    const int lane = threadIdx.x & 31;
    const int w    = threadIdx.x >> 5;           // sub 0..7
    const int hg   = blockIdx.x & 31;
    const int c    = (blockIdx.x >> 5) & (NC - 1);
    const int b    = blockIdx.x >> 9;
    const int h    = hg * 32 + lane;

    // aggregate 16 elements (newest on left)
    float4 agg = make_float4(1.0f, 0.0f, 0.0f, 0.0f);
    {
        const int s0 = c * (NW * NE) + w * NE;
        const float* vp = v + ((size_t)(b * PS + s0)) * (3 * PH) + h * 3;
        for (int i = 0; i < NE; i++) {
            agg = qmul(qfromv3(vp[0], vp[1], vp[2]), agg);
            vp += 3 * PH;
        }
    }
    *(float4*)(sub + ((((size_t)b * NC + c) * NW + w) * PH + h) * 4) = agg;

    // chunk total = agg7 * agg6 * ... * agg0
    __shared__ float4 sb[NW][32];
    sb[w][lane] = agg;
    __syncthreads();
    if (w == 0) {
        float4 tot = sb[0][lane];
#pragma unroll
        for (int j = 1; j < NW; j++) tot = qmul(sb[j][lane], tot);
        *(float4*)(part + (((size_t)b * NC + c) * PH + h) * 4) = tot;
    }
}

__global__ __launch_bounds__(256)
void scanC_kernel(const float* __restrict__ v, const float* __restrict__ sub,
                  const float* __restrict__ part, float* __restrict__ states,
                  float* __restrict__ mfinal) {
    const int lane = threadIdx.x & 31;
    const int w    = threadIdx.x >> 5;
    const int hg   = blockIdx.x & 31;
    const int c    = (blockIdx.x >> 5) & (NC - 1);
    const int b    = blockIdx.x >> 9;
    const int h    = hg * 32 + lane;

    // warp 0: exclusive chunk prefix = tot_{c-1} * ... * tot_0 (coalesced reads)
    __shared__ float4 pref_sh[32];
    if (w == 0) {
        float4 pref = make_float4(1.0f, 0.0f, 0.0f, 0.0f);
        for (int j = 0; j < c; j++) {
            float4 tot = *(const float4*)(part + (((size_t)b * NC + j) * PH + h) * 4);
            pref = qmul(tot, pref);
        }
        pref_sh[lane] = pref;
    }
    __syncthreads();

    // prefix = (subs w-1..0 of this chunk) * chunk exclusive prefix
    float4 p = pref_sh[lane];
    for (int j = 0; j < w; j++) {
        float4 sj = *(const float4*)(sub + ((((size_t)b * NC + c) * NW + j) * PH + h) * 4);
        p = qmul(sj, p);
    }

    const int s0 = c * (NW * NE) + w * NE;
    const float* vp = v + ((size_t)(b * PS + s0)) * (3 * PH) + h * 3;
    float* sp = states + (((size_t)(b * PS + s0)) * PH + h) * 4;
    for (int i = 0; i < NE; i++) {
        p = qmul(qfromv3(vp[0], vp[1], vp[2]), p);
        float4 oq = qnorm(p);
        *(float4*)sp = make_float4(tf32r(oq.x), tf32r(oq.y), tf32r(oq.z), tf32r(oq.w));
        if (c == NC - 1 && w == NW - 1 && i == NE - 1)
            *(float4*)(mfinal + ((size_t)b * PH + h) * 4) = oq;
        vp += 3 * PH;
        sp += (size_t)PH * 4;
    }
}

// ---------------------------------------------------------------------------
extern "C" void kernel_launch(void* const* d_in, const int* in_sizes, int n_in,
                              void* d_out, int out_size) {
    const float* x     = (const float*)d_in[0];   // (B,S,D)
    const float* W_in  = (const float*)d_in[1];   // (3H, D)
    const float* b_in  = (const float*)d_in[2];   // (3H)
    const float* W_out = (const float*)d_in[3];   // (D, 4H)
    const float* b_out = (const float*)d_in[4];   // (D)
    float* out = (float*)d_out;
    float* full_output = out;                      // (B,S,D)
    float* m_final     = out + (size_t)PM * PD;    // (B,H,4)

    float *v_ptr, *q_ptr, *wr, *subp, *partp;
    __nv_bfloat16 *ab, *bb;
    cudaGetSymbolAddress((void**)&v_ptr, g_v);
    cudaGetSymbolAddress((void**)&q_ptr, g_q);
    cudaGetSymbolAddress((void**)&wr, g_wr);
    cudaGetSymbolAddress((void**)&ab, g_ab);
    cudaGetSymbolAddress((void**)&bb, g_bb);
    cudaGetSymbolAddress((void**)&subp, g_sub);
    cudaGetSymbolAddress((void**)&partp, g_part);

    cudaFuncSetAttribute(gemm_mma<1>, cudaFuncAttributeMaxDynamicSharedMemorySize, GSMEM);
    cudaFuncSetAttribute(gemm_mma<0>, cudaFuncAttributeMaxDynamicSharedMemorySize, GSMEM);

    // fused prep: x/W_in bf16 3-term splits + W_out rna rounding (one launch)
    {
        unsigned grid = (unsigned)((PREP_TOTAL + 255) / 256);
        prep_kernel<<<grid, 256>>>(x, W_in, W_out, ab, bb, wr);
    }
    // GEMM1: v = x W_in^T + b_in  (M=8192, N=3072, K'=3072 bf16 3-term)
    {
        dim3 grid(3 * PH / BN, PM / BM);
        gemm_mma<1><<<grid, 256, GSMEM>>>((const char*)ab, (const char*)bb,
                                          b_in, v_ptr, 3 * PH, 3 * PD);
    }
    // two-phase coalesced exp-map + prefix quaternion scan (+ m_final)
    {
        const unsigned gridAC = PB * NC * (PH / 32);   // 2048
        scanA_kernel<<<gridAC, 256>>>(v_ptr, subp, partp);
        scanC_kernel<<<gridAC, 256>>>(v_ptr, subp, partp, q_ptr, m_final);
    }
    // GEMM2: out = states W_out^T + b_out  (M=8192, N=1024, K=4096 tf32)
    {
        dim3 grid(PD / BN, PM / BM);
        gemm_mma<0><<<grid, 256, GSMEM>>>((const char*)q_ptr, (const char*)wr,
                                          b_out, full_output, PD, 4 * PH);
    }
}

// round 13
// speedup vs baseline: 1.2006x; 1.0247x over previous
#include <cuda_runtime.h>
#include <cuda_bf16.h>
#include <math.h>
#include <stdint.h>

// Problem shapes (fixed): B=4, S=2048, D=1024, H=1024
#define PB 4
#define PS 2048
#define PD 1024
#define PH 1024
#define PM (PB * PS)          // 8192 rows
#define EPSQ 1e-8f

// scan decomposition: 16 chunks x 8 subs x 16 elements = 2048 = S
#define NC 16
#define NW 8
#define NE 16

// ---------------------------------------------------------------------------
// Static device scratch (allocation forbidden)
// ---------------------------------------------------------------------------
__device__ float g_v[(size_t)PM * (3 * PH)];                 // 8192 x 3072
__device__ float g_q[(size_t)PM * (4 * PH)];                 // 8192 x 4096 (states)
__device__ float g_wr[(size_t)PD * (4 * PH)];                // rna-rounded W_out
__device__ __nv_bfloat16 g_ab[(size_t)PM * (3 * PD)];        // x split [hi|lo|hi]
__device__ __nv_bfloat16 g_bb[(size_t)(3 * PH) * (3 * PD)];  // W_in split [hi|hi|lo]
__device__ float g_sub[(size_t)PB * NC * NW * PH * 4];       // sub aggregates
__device__ float g_part[(size_t)PB * NC * PH * 4];           // chunk TOTALS

// ---------------------------------------------------------------------------
// Helpers
// ---------------------------------------------------------------------------
__device__ __forceinline__ uint32_t smem_u32(const void* p) {
    uint32_t a;
    asm("{ .reg .u64 t; cvta.to.shared.u64 t, %1; cvt.u32.u64 %0, t; }" : "=r"(a) : "l"(p));
    return a;
}
__device__ __forceinline__ float tf32r(float a) {
    float r;
    asm("cvt.rna.tf32.f32 %0, %1;" : "=f"(r) : "f"(a));
    return r;
}
__device__ __forceinline__ float sqrt_approx(float a) {
    float r;
    asm("sqrt.approx.f32 %0, %1;" : "=f"(r) : "f"(a));
    return r;
}
__device__ __forceinline__ void cp_async16(uint32_t dst, const void* src) {
    asm volatile("cp.async.cg.shared.global [%0], [%1], 16;" :: "r"(dst), "l"(src));
}

#define MMA_TF32(acc, a0, a1, a2, a3, b0, b1) \
    asm volatile("mma.sync.aligned.m16n8k8.row.col.f32.tf32.tf32.f32 " \
        "{%0,%1,%2,%3}, {%4,%5,%6,%7}, {%8,%9}, {%0,%1,%2,%3};" \
        : "+f"((acc)[0]), "+f"((acc)[1]), "+f"((acc)[2]), "+f"((acc)[3]) \
        : "r"(a0), "r"(a1), "r"(a2), "r"(a3), "r"(b0), "r"(b1))

#define MMA_BF16(acc, a0, a1, a2, a3, b0, b1) \
    asm volatile("mma.sync.aligned.m16n8k16.row.col.f32.bf16.bf16.f32 " \
        "{%0,%1,%2,%3}, {%4,%5,%6,%7}, {%8,%9}, {%0,%1,%2,%3};" \
        : "+f"((acc)[0]), "+f"((acc)[1]), "+f"((acc)[2]), "+f"((acc)[3]) \
        : "r"(a0), "r"(a1), "r"(a2), "r"(a3), "r"(b0), "r"(b1))

// ---------------------------------------------------------------------------
// Unified mma.sync GEMM (proven config: CTA 128x128, 8 warps 2Mx4N of 64x32,
// 3-stage cp.async, XOR swizzle, 2 CTAs/SM).
//   BF16 == 1: bf16 elements, MMA m16n8k16;  BF16 == 0: fp32/tf32, m16n8k8
// K is in ELEMENTS.
// ---------------------------------------------------------------------------
#define BM 128
#define BN 128
#define GSTAGES 3
#define STAGE_BYTES 32768          // A 16KB + B 16KB
#define GSMEM (GSTAGES * STAGE_BYTES)

template<int BF16>
__global__ __launch_bounds__(256)
void gemm_mma(const char* __restrict__ A, const char* __restrict__ B,
              const float* __restrict__ bias, float* __restrict__ C,
              int N, int K) {
    extern __shared__ char smem[];
    const uint32_t sbase = smem_u32(smem);

    const int ESIZE = BF16 ? 2 : 4;
    const int KE = 128 / ESIZE;
    const int T = K / KE;

    const int tid = threadIdx.x;
    const int lane = tid & 31;
    const int wid = tid >> 5;
    const int wm = wid & 1;
    const int wn = wid >> 1;
    const int crow = blockIdx.y * BM;
    const int ccol = blockIdx.x * BN;

    const size_t rowBytes = (size_t)K * ESIZE;
    const char* Abase = A + (size_t)crow * rowBytes;
    const char* Bbase = B + (size_t)ccol * rowBytes;

    const int aHalf = lane >> 4;
    uint32_t aOff[4], aSwz[4];
#pragma unroll
    for (int mt = 0; mt < 4; mt++) {
        int r = wm * 64 + mt * 16 + (lane & 15);
        aOff[mt] = r * 128;
        aSwz[mt] = r & 7;
    }
    const int bHalf = (lane >> 3) & 1;
    uint32_t bOff[2], bSwz[2];
#pragma unroll
    for (int ntp = 0; ntp < 2; ntp++) {
        int r = wn * 32 + ntp * 16 + (lane & 7) + ((lane >> 4) << 3);
        bOff[ntp] = r * 128;
        bSwz[ntp] = r & 7;
    }

    float acc[4][4][4];
#pragma unroll
    for (int mt = 0; mt < 4; mt++)
#pragma unroll
        for (int nt = 0; nt < 4; nt++)
#pragma unroll
            for (int j = 0; j < 4; j++) acc[mt][nt][j] = 0.0f;

#define ISSUE(kt, stg) do { \
    _Pragma("unroll") \
    for (int _i = 0; _i < 4; _i++) { \
        int _s = tid + _i * 256; \
        int _row = _s >> 3, _c16 = _s & 7; \
        uint32_t _off = _row * 128 + ((_c16 ^ (_row & 7)) << 4); \
        const char* _asrc = Abase + (size_t)_row * rowBytes + (kt) * 128 + _c16 * 16; \
        const char* _bsrc = Bbase + (size_t)_row * rowBytes + (kt) * 128 + _c16 * 16; \
        cp_async16(sbase + (stg) * STAGE_BYTES + _off, _asrc); \
        cp_async16(sbase + (stg) * STAGE_BYTES + 16384 + _off, _bsrc); \
    } \
} while (0)

    ISSUE(0, 0);
    asm volatile("cp.async.commit_group;" ::: "memory");
    ISSUE(1, 1);
    asm volatile("cp.async.commit_group;" ::: "memory");

    for (int it = 0; it < T; ++it) {
        asm volatile("cp.async.wait_group 1;" ::: "memory");
        __syncthreads();
        if (it + 2 < T) ISSUE(it + 2, (it + 2) % GSTAGES);
        asm volatile("cp.async.commit_group;" ::: "memory");

        const uint32_t sA = sbase + (it % GSTAGES) * STAGE_BYTES;
        const uint32_t sB = sA + 16384;
#pragma unroll
        for (int ks = 0; ks < 4; ks++) {
            uint32_t aF[4][4];
#pragma unroll
            for (int mt = 0; mt < 4; mt++) {
                uint32_t ad = sA + aOff[mt] + (((2 * ks + aHalf) ^ aSwz[mt]) << 4);
                asm volatile("ldmatrix.sync.aligned.m8n8.x4.shared.b16 {%0,%1,%2,%3}, [%4];"
                    : "=r"(aF[mt][0]), "=r"(aF[mt][1]), "=r"(aF[mt][2]), "=r"(aF[mt][3])
                    : "r"(ad));
            }
            uint32_t bF[4][2];
#pragma unroll
            for (int ntp = 0; ntp < 2; ntp++) {
                uint32_t bd = sB + bOff[ntp] + (((2 * ks + bHalf) ^ bSwz[ntp]) << 4);
                asm volatile("ldmatrix.sync.aligned.m8n8.x4.shared.b16 {%0,%1,%2,%3}, [%4];"
                    : "=r"(bF[2 * ntp][0]), "=r"(bF[2 * ntp][1]),
                      "=r"(bF[2 * ntp + 1][0]), "=r"(bF[2 * ntp + 1][1])
                    : "r"(bd));
            }
#pragma unroll
            for (int mt = 0; mt < 4; mt++)
#pragma unroll
                for (int nt = 0; nt < 4; nt++) {
                    if constexpr (BF16) {
                        MMA_BF16(acc[mt][nt], aF[mt][0], aF[mt][1], aF[mt][2], aF[mt][3],
                                 bF[nt][0], bF[nt][1]);
                    } else {
                        MMA_TF32(acc[mt][nt], aF[mt][0], aF[mt][1], aF[mt][2], aF[mt][3],
                                 bF[nt][0], bF[nt][1]);
                    }
                }
        }
    }

    const int g = lane >> 2, tg = lane & 3;
#pragma unroll
    for (int mt = 0; mt < 4; mt++) {
        int r0 = crow + wm * 64 + mt * 16 + g;
#pragma unroll
        for (int nt = 0; nt < 4; nt++) {
            int col = ccol + wn * 32 + nt * 8 + 2 * tg;
            float2 bv = *(const float2*)(bias + col);
            float2 o0 = make_float2(acc[mt][nt][0] + bv.x, acc[mt][nt][1] + bv.y);
            float2 o1 = make_float2(acc[mt][nt][2] + bv.x, acc[mt][nt][3] + bv.y);
            *(float2*)(C + (size_t)r0 * N + col) = o0;
            *(float2*)(C + (size_t)(r0 + 8) * N + col) = o1;
        }
    }
#undef ISSUE
}

// ---------------------------------------------------------------------------
// Fused prep kernel (one launch): region 0 = x bf16-split [hi|lo|hi],
// region 1 = W_in bf16-split [hi|hi|lo], region 2 = W_out rna-tf32 round.
// ---------------------------------------------------------------------------
#define PREP_T0 ((size_t)PM * PD / 4)              // 2,097,152
#define PREP_T1 ((size_t)(3 * PH) * PD / 4)        //   786,432
#define PREP_T2 ((size_t)PD * (4 * PH) / 4)        // 1,048,576
#define PREP_TOTAL (PREP_T0 + PREP_T1 + PREP_T2)

__device__ __forceinline__ void split_bf16_one(const float* __restrict__ in,
                                               __nv_bfloat16* __restrict__ out,
                                               int K, int modeB, size_t s) {
    int K4 = K >> 2;
    size_t row = s / K4;
    int c4 = (int)(s - row * K4);
    float4 a = ((const float4*)in)[s];
    float av[4] = {a.x, a.y, a.z, a.w};
    __nv_bfloat16 h[4], l[4];
#pragma unroll
    for (int i = 0; i < 4; i++) {
        h[i] = __float2bfloat16_rn(av[i]);
        l[i] = __float2bfloat16_rn(av[i] - __bfloat162float(h[i]));
    }
    __nv_bfloat162 hv0, hv1, lv0, lv1;
    hv0.x = h[0]; hv0.y = h[1]; hv1.x = h[2]; hv1.y = h[3];
    lv0.x = l[0]; lv0.y = l[1]; lv1.x = l[2]; lv1.y = l[3];
    __nv_bfloat16* orow = out + row * (size_t)(3 * K);
    __nv_bfloat162* p0 = (__nv_bfloat162*)(orow + c4 * 4);
    __nv_bfloat162* p1 = (__nv_bfloat162*)(orow + K + c4 * 4);
    __nv_bfloat162* p2 = (__nv_bfloat162*)(orow + 2 * K + c4 * 4);
    p0[0] = hv0; p0[1] = hv1;
    if (modeB) { p1[0] = hv0; p1[1] = hv1; p2[0] = lv0; p2[1] = lv1; }
    else       { p1[0] = lv0; p1[1] = lv1; p2[0] = hv0; p2[1] = hv1; }
}

__global__ __launch_bounds__(256)
void prep_kernel(const float* __restrict__ x, const float* __restrict__ W_in,
                 const float* __restrict__ W_out,
                 __nv_bfloat16* __restrict__ ab, __nv_bfloat16* __restrict__ bb,
                 float* __restrict__ wr) {
    size_t gid = (size_t)blockIdx.x * 256 + threadIdx.x;
    if (gid < PREP_T0) {
        split_bf16_one(x, ab, PD, 0, gid);
    } else if (gid < PREP_T0 + PREP_T1) {
        split_bf16_one(W_in, bb, PD, 1, gid - PREP_T0);
    } else if (gid < PREP_TOTAL) {
        size_t s = gid - PREP_T0 - PREP_T1;
        float4 a = ((const float4*)W_out)[s];
        float4 r;
        r.x = tf32r(a.x); r.y = tf32r(a.y); r.z = tf32r(a.z); r.w = tf32r(a.w);
        ((float4*)wr)[s] = r;
    }
}

// ---------------------------------------------------------------------------
// Quaternion helpers (float4 = w,x,y,z) — MUFU fast-intrinsic versions.
// Per-step error ~1e-6, random-walks to ~4.5e-5 over S=2048: negligible vs
// the 3.66e-4 tf32 GEMM2 floor.
// ---------------------------------------------------------------------------
__device__ __forceinline__ float4 qmul(float4 a, float4 b) {
    return make_float4(
        a.x * b.x - a.y * b.y - a.z * b.z - a.w * b.w,
        a.x * b.y + a.y * b.x + a.z * b.w - a.w * b.z,
        a.x * b.z - a.y * b.w + a.z * b.x + a.w * b.y,
        a.x * b.w + a.y * b.z - a.z * b.y + a.w * b.x);
}
__device__ __forceinline__ float4 qnorm(float4 a) {
    float n2 = a.x * a.x + a.y * a.y + a.z * a.z + a.w * a.w;
    float s = rsqrtf(n2);          // prefix norms ~1; EPSQ term is O(1e-8) rel
    return make_float4(a.x * s, a.y * s, a.z * s, a.w * s);
}
__device__ __forceinline__ float4 qfromv3(float vx, float vy, float vz) {
    float th = sqrt_approx(vx * vx + vy * vy + vz * vz);   // exact 0 at 0
    float sn, cs;
    __sincosf(th, &sn, &cs);
    float inv = __fdividef(sn, th + EPSQ);
    return make_float4(cs, vx * inv, vy * inv, vz * inv);
}

// ---------------------------------------------------------------------------
// Two-phase coalesced quaternion scan (exclusive chunk-prefix folded into C).
// Grid A/C: B * NC * (H/32) = 2048 blocks, 256 threads = 32 h-lanes x NW subs.
// Newer-index-on-the-LEFT at every combine level.
// ---------------------------------------------------------------------------
__global__ __launch_bounds__(256)
void scanA_kernel(const float* __restrict__ v, float* __restrict__ sub,
                  float* __restrict__ part) {
    const int lane = threadIdx.x & 31;
    const int w    = threadIdx.x >> 5;           // sub 0..7
    const int hg   = blockIdx.x & 31;
    const int c    = (blockIdx.x >> 5) & (NC - 1);
    const int b    = blockIdx.x >> 9;
    const int h    = hg * 32 + lane;

    float4 agg = make_float4(1.0f, 0.0f, 0.0f, 0.0f);
    {
        const int s0 = c * (NW * NE) + w * NE;
        const float* vp = v + ((size_t)(b * PS + s0)) * (3 * PH) + h * 3;
        for (int i = 0; i < NE; i++) {
            agg = qmul(qfromv3(vp[0], vp[1], vp[2]), agg);
            vp += 3 * PH;
        }
    }
    *(float4*)(sub + ((((size_t)b * NC + c) * NW + w) * PH + h) * 4) = agg;

    __shared__ float4 sb[NW][32];
    sb[w][lane] = agg;
    __syncthreads();
    if (w == 0) {
        float4 tot = sb[0][lane];
#pragma unroll
        for (int j = 1; j < NW; j++) tot = qmul(sb[j][lane], tot);
        *(float4*)(part + (((size_t)b * NC + c) * PH + h) * 4) = tot;
    }
}

__global__ __launch_bounds__(256)
void scanC_kernel(const float* __restrict__ v, const float* __restrict__ sub,
                  const float* __restrict__ part, float* __restrict__ states,
                  float* __restrict__ mfinal) {
    const int lane = threadIdx.x & 31;
    const int w    = threadIdx.x >> 5;
    const int hg   = blockIdx.x & 31;
    const int c    = (blockIdx.x >> 5) & (NC - 1);
    const int b    = blockIdx.x >> 9;
    const int h    = hg * 32 + lane;

    __shared__ float4 pref_sh[32];
    if (w == 0) {
        float4 pref = make_float4(1.0f, 0.0f, 0.0f, 0.0f);
        for (int j = 0; j < c; j++) {
            float4 tot = *(const float4*)(part + (((size_t)b * NC + j) * PH + h) * 4);
            pref = qmul(tot, pref);
        }
        pref_sh[lane] = pref;
    }
    __syncthreads();

    float4 p = pref_sh[lane];
    for (int j = 0; j < w; j++) {
        float4 sj = *(const float4*)(sub + ((((size_t)b * NC + c) * NW + j) * PH + h) * 4);
        p = qmul(sj, p);
    }

    const int s0 = c * (NW * NE) + w * NE;
    const float* vp = v + ((size_t)(b * PS + s0)) * (3 * PH) + h * 3;
    float* sp = states + (((size_t)(b * PS + s0)) * PH + h) * 4;
    for (int i = 0; i < NE; i++) {
        p = qmul(qfromv3(vp[0], vp[1], vp[2]), p);
        float4 oq = qnorm(p);
        *(float4*)sp = make_float4(tf32r(oq.x), tf32r(oq.y), tf32r(oq.z), tf32r(oq.w));
        if (c == NC - 1 && w == NW - 1 && i == NE - 1)
            *(float4*)(mfinal + ((size_t)b * PH + h) * 4) = oq;
        vp += 3 * PH;
        sp += (size_t)PH * 4;
    }
}

// ---------------------------------------------------------------------------
extern "C" void kernel_launch(void* const* d_in, const int* in_sizes, int n_in,
                              void* d_out, int out_size) {
    const float* x     = (const float*)d_in[0];   // (B,S,D)
    const float* W_in  = (const float*)d_in[1];   // (3H, D)
    const float* b_in  = (const float*)d_in[2];   // (3H)
    const float* W_out = (const float*)d_in[3];   // (D, 4H)
    const float* b_out = (const float*)d_in[4];   // (D)
    float* out = (float*)d_out;
    float* full_output = out;                      // (B,S,D)
    float* m_final     = out + (size_t)PM * PD;    // (B,H,4)

    float *v_ptr, *q_ptr, *wr, *subp, *partp;
    __nv_bfloat16 *ab, *bb;
    cudaGetSymbolAddress((void**)&v_ptr, g_v);
    cudaGetSymbolAddress((void**)&q_ptr, g_q);
    cudaGetSymbolAddress((void**)&wr, g_wr);
    cudaGetSymbolAddress((void**)&ab, g_ab);
    cudaGetSymbolAddress((void**)&bb, g_bb);
    cudaGetSymbolAddress((void**)&subp, g_sub);
    cudaGetSymbolAddress((void**)&partp, g_part);

    cudaFuncSetAttribute(gemm_mma<1>, cudaFuncAttributeMaxDynamicSharedMemorySize, GSMEM);
    cudaFuncSetAttribute(gemm_mma<0>, cudaFuncAttributeMaxDynamicSharedMemorySize, GSMEM);

    // fused prep: x/W_in bf16 3-term splits + W_out rna rounding (one launch)
    {
        unsigned grid = (unsigned)((PREP_TOTAL + 255) / 256);
        prep_kernel<<<grid, 256>>>(x, W_in, W_out, ab, bb, wr);
    }
    // GEMM1: v = x W_in^T + b_in  (M=8192, N=3072, K'=3072 bf16 3-term)
    {
        dim3 grid(3 * PH / BN, PM / BM);
        gemm_mma<1><<<grid, 256, GSMEM>>>((const char*)ab, (const char*)bb,
                                          b_in, v_ptr, 3 * PH, 3 * PD);
    }
    // two-phase coalesced exp-map + prefix quaternion scan (+ m_final)
    {
        const unsigned gridAC = PB * NC * (PH / 32);   // 2048
        scanA_kernel<<<gridAC, 256>>>(v_ptr, subp, partp);
        scanC_kernel<<<gridAC, 256>>>(v_ptr, subp, partp, q_ptr, m_final);
    }
    // GEMM2: out = states W_out^T + b_out  (M=8192, N=1024, K=4096 tf32)
    {
        dim3 grid(PD / BN, PM / BM);
        gemm_mma<0><<<grid, 256, GSMEM>>>((const char*)q_ptr, (const char*)wr,
                                          b_out, full_output, PD, 4 * PH);
    }
}